// round 15
// baseline (speedup 1.0000x reference)
#include <cuda_runtime.h>
#include <cuda_bf16.h>
#include <cuda_fp16.h>
#include <cooperative_groups.h>
#include <cstdint>

namespace cg = cooperative_groups;

#define NN 100000
#define NE 1600000
#define NBLK ((NN + 255) / 256)

// ---------------- static device scratch (allocation-free) ----------------
__device__ int    g_cnt[NN];
__device__ int    g_rowptr[NN + 1];
__device__ int    g_cursor[NN];
__device__ int    g_colidx[NE];
__device__ float  g_deginv[NN];
__device__ float  g_Ys[(size_t)NN * 64];   // self-term GEMM output (fp32)
__device__ __half g_Yh[(size_t)NN * 64];   // neighbor-term GEMM output (fp16)
__device__ float  g_H[(size_t)NN * 64];    // hidden activations (pre-BN)
__device__ float  g_stat1[192];            // per-layer BN sums (3 x 64)
__device__ float  g_stat2[192];            // per-layer BN sumsq
__device__ int    g_bsum[512];
__device__ int    g_boff[512];
__device__ uint4  g_Bf[8704];              // packed B frags: L1@0, L2@4096, L3@6144, L4@8192

// ---------------- helpers ----------------
__device__ __forceinline__ void split2(float v0, float v1,
                                       uint32_t& h, uint32_t& l) {
    __nv_bfloat162 hp = __floats2bfloat162_rn(v0, v1);
    float r0 = v0 - __low2float(hp);
    float r1 = v1 - __high2float(hp);
    __nv_bfloat162 lp = __floats2bfloat162_rn(r0, r1);
    h = *(uint32_t*)&hp;
    l = *(uint32_t*)&lp;
}

__device__ __forceinline__ void mma_bf16(float* c, const uint4& a,
                                         uint32_t b0, uint32_t b1) {
    asm volatile(
        "mma.sync.aligned.m16n8k16.row.col.f32.bf16.bf16.f32 "
        "{%0,%1,%2,%3}, {%4,%5,%6,%7}, {%8,%9}, {%0,%1,%2,%3};"
        : "+f"(c[0]), "+f"(c[1]), "+f"(c[2]), "+f"(c[3])
        : "r"(a.x), "r"(a.y), "r"(a.z), "r"(a.w), "r"(b0), "r"(b1));
}

// ---------------- CSR build (R8-proven versions) ----------------
__global__ void k_init() {
    int i = blockIdx.x * 256 + threadIdx.x;
    if (i < NN) g_cnt[i] = 0;
    if (i < 192) { g_stat1[i] = 0.f; g_stat2[i] = 0.f; }
}

__global__ void k_hist(const int* __restrict__ dst) {
    int e = blockIdx.x * 256 + threadIdx.x;
    if (e < NE) atomicAdd(&g_cnt[dst[e]], 1);
}

__global__ void k_scan_block() {
    __shared__ int sh[256];
    int i = blockIdx.x * 256 + threadIdx.x;
    int v = (i < NN) ? g_cnt[i] : 0;
    sh[threadIdx.x] = v;
    __syncthreads();
    #pragma unroll
    for (int off = 1; off < 256; off <<= 1) {
        int t = (threadIdx.x >= off) ? sh[threadIdx.x - off] : 0;
        __syncthreads();
        sh[threadIdx.x] += t;
        __syncthreads();
    }
    if (i < NN) g_rowptr[i] = sh[threadIdx.x] - v;
    if (threadIdx.x == 255) g_bsum[blockIdx.x] = sh[255];
}

__global__ void k_scan_tops(int nb) {
    __shared__ int sh[512];
    int t = threadIdx.x;
    int v = (t < nb) ? g_bsum[t] : 0;
    sh[t] = v;
    __syncthreads();
    #pragma unroll
    for (int off = 1; off < 512; off <<= 1) {
        int tt = (t >= off) ? sh[t - off] : 0;
        __syncthreads();
        sh[t] += tt;
        __syncthreads();
    }
    g_boff[t] = sh[t] - v;
}

__global__ void k_scan_add() {
    int i = blockIdx.x * 256 + threadIdx.x;
    if (i < NN) {
        int rp = g_rowptr[i] + g_boff[blockIdx.x];
        g_rowptr[i] = rp;
        g_cursor[i] = rp;
        int c = g_cnt[i];
        g_deginv[i] = 1.0f / (float)(c > 1 ? c : 1);
    }
    if (blockIdx.x == 0 && threadIdx.x == 0) g_rowptr[NN] = NE;
}

__global__ void k_fill(const int* __restrict__ src, const int* __restrict__ dst) {
    int e = blockIdx.x * 256 + threadIdx.x;
    if (e < NE) {
        int d = dst[e];
        int p = atomicAdd(&g_cursor[d], 1);
        g_colidx[p] = src[e];
    }
}

// ---------------- B fragment pack (all 4 layers, bf16 hi/lo) ----------------
__device__ __forceinline__ void bpack_one(int idx, int base, int K, int NC,
                                          const float* __restrict__ Ws,
                                          const float* __restrict__ Wn) {
    int F = NC / 2, NT = NC / 8;
    int lane = idx & 31, t = (idx >> 5) % NT, s = (idx >> 5) / NT;
    int c = lane & 3, gn = lane >> 2;
    int n = t * 8 + gn;
    int k0 = s * 16 + 2 * c;
    const float* W = (n < F) ? Ws : Wn;
    int nn = (n < F) ? n : n - F;
    float w00 = W[(k0    ) * F + nn];
    float w01 = W[(k0 + 1) * F + nn];
    float w10 = W[(k0 + 8) * F + nn];
    float w11 = W[(k0 + 9) * F + nn];
    uint4 q;
    split2(w00, w01, q.x, q.z);
    split2(w10, w11, q.y, q.w);
    g_Bf[base + idx] = q;
}

__global__ void k_bpack_all(const float* Ws1, const float* Wn1,
                            const float* Ws2, const float* Wn2,
                            const float* Ws3, const float* Wn3,
                            const float* Ws4, const float* Wn4) {
    int i = blockIdx.x * 256 + threadIdx.x;
    if      (i < 4096) bpack_one(i,        0,    128, 128, Ws1, Wn1);
    else if (i < 6144) bpack_one(i - 4096, 4096, 64,  128, Ws2, Wn2);
    else if (i < 8192) bpack_one(i - 6144, 6144, 64,  128, Ws3, Wn3);
    else if (i < 8704) bpack_one(i - 8192, 8192, 64,  32,  Ws4, Wn4);
}

// ---------------- GEMM body (R12 v2): B-in-smem, grid-stride tiles ---------
template <int K, int NC, bool AFF, bool RELU>
__device__ void gemm_body(
    const float* __restrict__ A, const uint4* __restrict__ Bf,
    float* __restrict__ Ys, __half* __restrict__ Yh,
    const float* __restrict__ s1, const float* __restrict__ s2,
    const float* __restrict__ gamma, const float* __restrict__ beta,
    int M, int ntiles, uint4* sB, float* sAff)
{
    constexpr int KS    = K / 16;
    constexpr int NTall = NC / 8;
    constexpr int F     = NC / 2;
    constexpr int CGRP  = (NC >= 128) ? 2 : 1;
    constexpr int CPW   = NC / CGRP;
    constexpr int NT    = CPW / 8;
    constexpr int RGRP  = 8 / CGRP;
    constexpr int RPW   = 128 / RGRP;
    constexpr int NROW  = RPW / 16;
    constexpr int SBN   = KS * NTall * 32;

    const int tid  = threadIdx.x;
    const int wid  = tid >> 5, lane = tid & 31;
    const int rw   = wid % RGRP, cw = wid / RGRP;
    const int g    = lane >> 2, c = lane & 3;

    for (int i = tid; i < SBN; i += 256) sB[i] = Bf[i];
    if (AFF) {
        if (tid < 64) {
            const float invN = 1.0f / (float)NN;
            float m   = s1[tid] * invN;
            float var = s2[tid] * invN - m * m;
            float r   = rsqrtf(var + 1e-5f);
            float a   = r * gamma[tid];
            sAff[tid]      = a;
            sAff[64 + tid] = fmaf(-m, a, beta[tid]);
        }
    }
    __syncthreads();

    for (int tile = blockIdx.x; tile < ntiles; tile += gridDim.x) {
        const int rowb = tile * 128 + rw * RPW;

        float acc[NROW][NT][4];
        #pragma unroll
        for (int rr = 0; rr < NROW; rr++)
            #pragma unroll
            for (int t = 0; t < NT; t++)
                #pragma unroll
                for (int j = 0; j < 4; j++) acc[rr][t][j] = 0.f;

        #pragma unroll
        for (int s = 0; s < KS; s++) {
            const int k0 = s * 16 + 2 * c;
            uint4 ah[NROW], al[NROW];
            #pragma unroll
            for (int rr = 0; rr < NROW; rr++) {
                int r0 = rowb + rr * 16 + g, r1 = r0 + 8;
                float2 v00 = (r0 < M) ? *(const float2*)(A + (size_t)r0 * K + k0)
                                      : make_float2(0.f, 0.f);
                float2 v01 = (r0 < M) ? *(const float2*)(A + (size_t)r0 * K + k0 + 8)
                                      : make_float2(0.f, 0.f);
                float2 v10 = (r1 < M) ? *(const float2*)(A + (size_t)r1 * K + k0)
                                      : make_float2(0.f, 0.f);
                float2 v11 = (r1 < M) ? *(const float2*)(A + (size_t)r1 * K + k0 + 8)
                                      : make_float2(0.f, 0.f);
                if (AFF) {
                    float a0 = sAff[k0],     c0 = sAff[64 + k0];
                    float a1 = sAff[k0 + 1], c1 = sAff[64 + k0 + 1];
                    float a2 = sAff[k0 + 8], c2 = sAff[64 + k0 + 8];
                    float a3 = sAff[k0 + 9], c3 = sAff[64 + k0 + 9];
                    v00.x = fmaf(v00.x, a0, c0); v00.y = fmaf(v00.y, a1, c1);
                    v10.x = fmaf(v10.x, a0, c0); v10.y = fmaf(v10.y, a1, c1);
                    v01.x = fmaf(v01.x, a2, c2); v01.y = fmaf(v01.y, a3, c3);
                    v11.x = fmaf(v11.x, a2, c2); v11.y = fmaf(v11.y, a3, c3);
                    if (RELU) {
                        v00.x = fmaxf(v00.x, 0.f); v00.y = fmaxf(v00.y, 0.f);
                        v01.x = fmaxf(v01.x, 0.f); v01.y = fmaxf(v01.y, 0.f);
                        v10.x = fmaxf(v10.x, 0.f); v10.y = fmaxf(v10.y, 0.f);
                        v11.x = fmaxf(v11.x, 0.f); v11.y = fmaxf(v11.y, 0.f);
                    }
                }
                split2(v00.x, v00.y, ah[rr].x, al[rr].x);
                split2(v10.x, v10.y, ah[rr].y, al[rr].y);
                split2(v01.x, v01.y, ah[rr].z, al[rr].z);
                split2(v11.x, v11.y, ah[rr].w, al[rr].w);
            }
            const uint4* bp = sB + (size_t)(s * NTall + cw * NT) * 32 + lane;
            #pragma unroll
            for (int t = 0; t < NT; t++) {
                uint4 b = bp[t * 32];
                #pragma unroll
                for (int rr = 0; rr < NROW; rr++) {
                    mma_bf16(acc[rr][t], ah[rr], b.x, b.y);
                    mma_bf16(acc[rr][t], ah[rr], b.z, b.w);
                    mma_bf16(acc[rr][t], al[rr], b.x, b.y);
                }
            }
        }

        #pragma unroll
        for (int rr = 0; rr < NROW; rr++) {
            int r0 = rowb + rr * 16 + g, r1 = r0 + 8;
            #pragma unroll
            for (int t = 0; t < NT; t++) {
                int base = cw * CPW + t * 8;
                if (base < F) {
                    int col = base + 2 * c;
                    if (r0 < M)
                        *(float2*)(Ys + (size_t)r0 * F + col) =
                            make_float2(acc[rr][t][0], acc[rr][t][1]);
                    if (r1 < M)
                        *(float2*)(Ys + (size_t)r1 * F + col) =
                            make_float2(acc[rr][t][2], acc[rr][t][3]);
                } else {
                    int col = base - F + 2 * c;
                    if (r0 < M)
                        *(__half2*)(Yh + (size_t)r0 * F + col) =
                            __floats2half2_rn(acc[rr][t][0], acc[rr][t][1]);
                    if (r1 < M)
                        *(__half2*)(Yh + (size_t)r1 * F + col) =
                            __floats2half2_rn(acc[rr][t][2], acc[rr][t][3]);
                }
            }
        }
    }
}

// ---------------- agg bodies ----------------
__device__ void agg64_body(const float* __restrict__ Ys, const __half2* __restrict__ Yh,
                           const float* __restrict__ bias, float* __restrict__ H,
                           float* __restrict__ s1, float* __restrict__ s2,
                           int M, float* ss)
{
    int tid = threadIdx.x;
    if (tid < 128) ss[tid] = 0.f;
    __syncthreads();

    int lane = tid & 31, w = tid >> 5;
    int c0 = lane * 2;
    float bx = bias[c0], by = bias[c0 + 1];
    float p1 = 0.f, p2 = 0.f, q1 = 0.f, q2 = 0.f;

    for (int v = blockIdx.x * 8 + w; v < M; v += gridDim.x * 8) {
        int beg = g_rowptr[v], end = g_rowptr[v + 1];
        float ax0 = 0.f, ay0 = 0.f, ax1 = 0.f, ay1 = 0.f;
        float ax2 = 0.f, ay2 = 0.f, ax3 = 0.f, ay3 = 0.f;
        int e = beg;
        for (; e + 4 <= end; e += 4) {
            int s0 = g_colidx[e],     s1i = g_colidx[e + 1];
            int s2i = g_colidx[e + 2], s3 = g_colidx[e + 3];
            float2 t0 = __half22float2(Yh[(size_t)s0  * 32 + lane]);
            float2 t1 = __half22float2(Yh[(size_t)s1i * 32 + lane]);
            float2 t2 = __half22float2(Yh[(size_t)s2i * 32 + lane]);
            float2 t3 = __half22float2(Yh[(size_t)s3  * 32 + lane]);
            ax0 += t0.x; ay0 += t0.y;
            ax1 += t1.x; ay1 += t1.y;
            ax2 += t2.x; ay2 += t2.y;
            ax3 += t3.x; ay3 += t3.y;
        }
        for (; e < end; e++) {
            int s = g_colidx[e];
            float2 t = __half22float2(Yh[(size_t)s * 32 + lane]);
            ax0 += t.x; ay0 += t.y;
        }
        float ax = (ax0 + ax1) + (ax2 + ax3);
        float ay = (ay0 + ay1) + (ay2 + ay3);
        float di = g_deginv[v];
        float2 ys = *(const float2*)(Ys + (size_t)v * 64 + c0);
        float hx = fmaf(ax, di, ys.x) + bx;
        float hy = fmaf(ay, di, ys.y) + by;
        *(float2*)(H + (size_t)v * 64 + c0) = make_float2(hx, hy);
        p1 += hx; p2 += hx * hx;
        q1 += hy; q2 += hy * hy;
    }
    atomicAdd(&ss[c0], p1);      atomicAdd(&ss[64 + c0], p2);
    atomicAdd(&ss[c0 + 1], q1);  atomicAdd(&ss[64 + c0 + 1], q2);
    __syncthreads();
    if (tid < 64) {
        atomicAdd(&s1[tid], ss[tid]);
        atomicAdd(&s2[tid], ss[64 + tid]);
    }
}

__device__ void agg16_body(const float* __restrict__ Ys, const __half* __restrict__ Yh,
                           const float* __restrict__ bias, float* __restrict__ O, int M)
{
    int tid = threadIdx.x, lane = tid & 31, w = tid >> 5;
    bool act = lane < 16;
    float b = act ? bias[lane] : 0.f;
    for (int v = blockIdx.x * 8 + w; v < M; v += gridDim.x * 8) {
        int beg = g_rowptr[v], end = g_rowptr[v + 1];
        float a0 = 0.f, a1 = 0.f, a2 = 0.f, a3 = 0.f;
        int e = beg;
        for (; e + 4 <= end; e += 4) {
            int s0 = g_colidx[e],     s1 = g_colidx[e + 1];
            int s2 = g_colidx[e + 2], s3 = g_colidx[e + 3];
            if (act) {
                float t0 = __half2float(Yh[(size_t)s0 * 16 + lane]);
                float t1 = __half2float(Yh[(size_t)s1 * 16 + lane]);
                float t2 = __half2float(Yh[(size_t)s2 * 16 + lane]);
                float t3 = __half2float(Yh[(size_t)s3 * 16 + lane]);
                a0 += t0; a1 += t1; a2 += t2; a3 += t3;
            }
        }
        for (; e < end; e++) {
            int s = g_colidx[e];
            if (act) a0 += __half2float(Yh[(size_t)s * 16 + lane]);
        }
        if (act) {
            float a = (a0 + a1) + (a2 + a3);
            float ys = Ys[(size_t)v * 16 + lane];
            O[(size_t)v * 16 + lane] = fmaf(a, g_deginv[v], ys) + b;
        }
    }
}

// ---------------- standalone GEMM kernel (layer 1) ----------------
template <int K, int NC, bool AFF, bool RELU>
__global__ __launch_bounds__(256, 2) void k_mma(
    const float* __restrict__ A, const uint4* __restrict__ Bf,
    float* __restrict__ Ys, __half* __restrict__ Yh,
    const float* __restrict__ s1, const float* __restrict__ s2,
    const float* __restrict__ gamma, const float* __restrict__ beta,
    int M, int ntiles)
{
    extern __shared__ char smem[];
    uint4* sB   = (uint4*)smem;
    float* sAff = (float*)(smem + (size_t)K * NC * 4);
    gemm_body<K, NC, AFF, RELU>(A, Bf, Ys, Yh, s1, s2, gamma, beta,
                                M, ntiles, sB, sAff);
}

// ---------------- megakernel: agg1 -> L2 -> L3 -> L4 -> agg16 --------------
// One cooperative persistent kernel; grid.sync() between phases replaces
// 6 kernel-launch gaps.
__global__ __launch_bounds__(256, 2) void k_mega(
    float* Ys, __half* Yh, float* H, float* out, const uint4* Bf,
    const float* b1, const float* g1, const float* be1,
    const float* b2, const float* g2, const float* be2,
    const float* b3, const float* g3, const float* be3,
    const float* b4,
    float* st1, float* st2, int M, int ntiles)
{
    extern __shared__ char smem[];
    uint4* sB   = (uint4*)smem;
    float* sAff = (float*)(smem + 32768);
    float* ss   = sAff + 128;
    cg::grid_group grid = cg::this_grid();

    // layer 1 aggregation (+ BN1 stats)
    agg64_body(Ys, (const __half2*)Yh, b1, H, st1, st2, M, ss);
    grid.sync();

    // layer 2: GEMM (BN1 affine folded) + aggregation (+ BN2 stats)
    gemm_body<64, 128, true, false>(H, Bf + 4096, Ys, Yh, st1, st2, g1, be1,
                                    M, ntiles, sB, sAff);
    grid.sync();
    agg64_body(Ys, (const __half2*)Yh, b2, H, st1 + 64, st2 + 64, M, ss);
    grid.sync();

    // layer 3
    gemm_body<64, 128, true, true>(H, Bf + 6144, Ys, Yh, st1 + 64, st2 + 64,
                                   g2, be2, M, ntiles, sB, sAff);
    grid.sync();
    agg64_body(Ys, (const __half2*)Yh, b3, H, st1 + 128, st2 + 128, M, ss);
    grid.sync();

    // layer 4 (out = 16 cols)
    gemm_body<64, 32, true, true>(H, Bf + 8192, Ys, Yh, st1 + 128, st2 + 128,
                                  g3, be3, M, ntiles, sB, sAff);
    grid.sync();
    agg16_body(Ys, Yh, b4, out, M);
}

// ---------------- launch ----------------
static constexpr int smem_b(int K, int NC) { return K * NC * 4 + 512; }
static constexpr int SMEM_MEGA = 32768 + 512 + 512;

extern "C" void kernel_launch(void* const* d_in, const int* in_sizes, int n_in,
                              void* d_out, int out_size)
{
    const float* x   = (const float*)d_in[0];
    const int*   src = (const int*)d_in[1];
    const int*   dst = (const int*)d_in[2];
    const float* Ws1 = (const float*)d_in[3];
    const float* Wn1 = (const float*)d_in[4];
    const float* b1  = (const float*)d_in[5];
    const float* g1  = (const float*)d_in[6];
    const float* be1 = (const float*)d_in[7];
    const float* Ws2 = (const float*)d_in[8];
    const float* Wn2 = (const float*)d_in[9];
    const float* b2  = (const float*)d_in[10];
    const float* g2  = (const float*)d_in[11];
    const float* be2 = (const float*)d_in[12];
    const float* Ws3 = (const float*)d_in[13];
    const float* Wn3 = (const float*)d_in[14];
    const float* b3  = (const float*)d_in[15];
    const float* g3  = (const float*)d_in[16];
    const float* be3 = (const float*)d_in[17];
    const float* Ws4 = (const float*)d_in[18];
    const float* Wn4 = (const float*)d_in[19];
    const float* b4  = (const float*)d_in[20];
    float* out = (float*)d_out;

    float *Ysp, *Hp, *st1, *st2;
    __half* Yhp;
    uint4* Bfp;
    cudaGetSymbolAddress((void**)&Ysp, g_Ys);
    cudaGetSymbolAddress((void**)&Yhp, g_Yh);
    cudaGetSymbolAddress((void**)&Hp,  g_H);
    cudaGetSymbolAddress((void**)&st1, g_stat1);
    cudaGetSymbolAddress((void**)&st2, g_stat2);
    cudaGetSymbolAddress((void**)&Bfp, g_Bf);

    const int EB = (NE + 255) / 256;
    int NT128 = (NN + 127) / 128;   // 782 row tiles
    int Mv = NN;
    const int GMMA = 296;           // 2 CTAs/SM, persistent

    cudaFuncSetAttribute(k_mma<128, 128, false, false>,
        cudaFuncAttributeMaxDynamicSharedMemorySize, smem_b(128, 128));
    cudaFuncSetAttribute(k_mega,
        cudaFuncAttributeMaxDynamicSharedMemorySize, SMEM_MEGA);

    // Side stream + fork/join events (created on the two host-executed calls
    // only; replays re-execute captured GPU nodes).
    cudaStream_t s2;
    cudaStreamCreate(&s2);
    cudaEvent_t evFork, evJoin;
    cudaEventCreateWithFlags(&evFork, cudaEventDisableTiming);
    cudaEventCreateWithFlags(&evJoin, cudaEventDisableTiming);

    // main stream: zero counters/stats, then fork
    k_init<<<NBLK, 256>>>();
    cudaEventRecord(evFork, 0);
    cudaStreamWaitEvent(s2, evFork, 0);

    // side stream: CSC (dst-grouped) build — independent of GEMM1/bpack
    k_hist<<<EB, 256, 0, s2>>>(dst);
    k_scan_block<<<NBLK, 256, 0, s2>>>();
    k_scan_tops<<<1, 512, 0, s2>>>(NBLK);
    k_scan_add<<<NBLK, 256, 0, s2>>>();
    k_fill<<<EB, 256, 0, s2>>>(src, dst);
    cudaEventRecord(evJoin, s2);

    // main stream (concurrent with CSC build): weight pack + layer-1 GEMM
    k_bpack_all<<<34, 256>>>(Ws1, Wn1, Ws2, Wn2, Ws3, Wn3, Ws4, Wn4);
    k_mma<128, 128, false, false><<<GMMA, 256, smem_b(128, 128)>>>(
        x, Bfp, Ysp, Yhp, nullptr, nullptr, nullptr, nullptr, NN, NT128);

    // join: the megakernel needs both GEMM1 output and the CSC structure
    cudaStreamWaitEvent(0, evJoin, 0);

    // megakernel: agg1 -> gemm2 -> agg2 -> gemm3 -> agg3 -> gemm4 -> agg16
    void* margs[] = {
        &Ysp, &Yhp, &Hp, &out, &Bfp,
        (void*)&b1, (void*)&g1, (void*)&be1,
        (void*)&b2, (void*)&g2, (void*)&be2,
        (void*)&b3, (void*)&g3, (void*)&be3,
        (void*)&b4,
        &st1, &st2, &Mv, &NT128
    };
    cudaLaunchCooperativeKernel((void*)k_mega, dim3(GMMA), dim3(256),
                                margs, SMEM_MEGA, 0);
}

// round 16
// speedup vs baseline: 1.4324x; 1.4324x over previous
#include <cuda_runtime.h>
#include <cuda_fp16.h>
#include <cstdint>

#define NN 100000
#define NE 1600000
#define NBLK ((NN + 255) / 256)

// ---------------- static device scratch (allocation-free) ----------------
__device__ int    g_cnt[NN];
__device__ int    g_rowptr[NN + 1];
__device__ int    g_cursor[NN];
__device__ int    g_colidx[NE];
__device__ float  g_deginv[NN];
__device__ float  g_Ys[(size_t)NN * 64];   // self-term GEMM output (fp32)
__device__ __half g_Yh[(size_t)NN * 64];   // neighbor-term GEMM output (fp16)
__device__ float  g_H[(size_t)NN * 64];    // hidden activations (pre-BN)
__device__ float  g_stat1[192];            // per-layer BN sums (3 x 64)
__device__ float  g_stat2[192];            // per-layer BN sumsq
__device__ int    g_bsum[512];
__device__ int    g_boff[512];
// tf32 B fragments: L1@0 (8192), L2@8192 (4096), L3@12288 (4096), L4@16384 (1024)
__device__ uint2  g_Bf[17408];

// ---------------- helpers ----------------
__device__ __forceinline__ uint32_t f2tf32(float v) {
    uint32_t u;
    asm("cvt.rna.tf32.f32 %0, %1;" : "=r"(u) : "f"(v));
    return u;
}

// m16n8k8 tf32 MMA, fp32 accumulate
__device__ __forceinline__ void mma_tf32(float* c, const uint32_t* a,
                                         uint32_t b0, uint32_t b1) {
    asm volatile(
        "mma.sync.aligned.m16n8k8.row.col.f32.tf32.tf32.f32 "
        "{%0,%1,%2,%3}, {%4,%5,%6,%7}, {%8,%9}, {%0,%1,%2,%3};"
        : "+f"(c[0]), "+f"(c[1]), "+f"(c[2]), "+f"(c[3])
        : "r"(a[0]), "r"(a[1]), "r"(a[2]), "r"(a[3]), "r"(b0), "r"(b1));
}

// ---------------- CSR build (R8-proven versions) ----------------
__global__ void k_init() {
    int i = blockIdx.x * 256 + threadIdx.x;
    if (i < NN) g_cnt[i] = 0;
    if (i < 192) { g_stat1[i] = 0.f; g_stat2[i] = 0.f; }
}

__global__ void k_hist(const int* __restrict__ dst) {
    int e = blockIdx.x * 256 + threadIdx.x;
    if (e < NE) atomicAdd(&g_cnt[dst[e]], 1);
}

__global__ void k_scan_block() {
    __shared__ int sh[256];
    int i = blockIdx.x * 256 + threadIdx.x;
    int v = (i < NN) ? g_cnt[i] : 0;
    sh[threadIdx.x] = v;
    __syncthreads();
    #pragma unroll
    for (int off = 1; off < 256; off <<= 1) {
        int t = (threadIdx.x >= off) ? sh[threadIdx.x - off] : 0;
        __syncthreads();
        sh[threadIdx.x] += t;
        __syncthreads();
    }
    if (i < NN) g_rowptr[i] = sh[threadIdx.x] - v;
    if (threadIdx.x == 255) g_bsum[blockIdx.x] = sh[255];
}

__global__ void k_scan_tops(int nb) {
    __shared__ int sh[512];
    int t = threadIdx.x;
    int v = (t < nb) ? g_bsum[t] : 0;
    sh[t] = v;
    __syncthreads();
    #pragma unroll
    for (int off = 1; off < 512; off <<= 1) {
        int tt = (t >= off) ? sh[t - off] : 0;
        __syncthreads();
        sh[t] += tt;
        __syncthreads();
    }
    g_boff[t] = sh[t] - v;
}

__global__ void k_scan_add() {
    int i = blockIdx.x * 256 + threadIdx.x;
    if (i < NN) {
        int rp = g_rowptr[i] + g_boff[blockIdx.x];
        g_rowptr[i] = rp;
        g_cursor[i] = rp;
        int c = g_cnt[i];
        g_deginv[i] = 1.0f / (float)(c > 1 ? c : 1);
    }
    if (blockIdx.x == 0 && threadIdx.x == 0) g_rowptr[NN] = NE;
}

__global__ void k_fill(const int* __restrict__ src, const int* __restrict__ dst) {
    int e = blockIdx.x * 256 + threadIdx.x;
    if (e < NE) {
        int d = dst[e];
        int p = atomicAdd(&g_cursor[d], 1);
        g_colidx[p] = src[e];
    }
}

// ---------------- B fragment pack (tf32, m16n8k8 col-major layout) ---------
// entry (s8, t, lane): b0 = W'[k = s8*8 + c][n = t*8 + g], b1 = k+4
__device__ __forceinline__ void bpack_one(int idx, int base, int K, int NC,
                                          const float* __restrict__ Ws,
                                          const float* __restrict__ Wn) {
    int F = NC / 2, NT = NC / 8;
    int lane = idx & 31, t = (idx >> 5) % NT, s8 = (idx >> 5) / NT;
    int c = lane & 3, gn = lane >> 2;
    int n = t * 8 + gn;
    int k0 = s8 * 8 + c;
    const float* W = (n < F) ? Ws : Wn;
    int nn = (n < F) ? n : n - F;
    float w0 = W[(k0    ) * F + nn];
    float w1 = W[(k0 + 4) * F + nn];
    g_Bf[base + idx] = make_uint2(f2tf32(w0), f2tf32(w1));
}

__global__ void k_bpack_all(const float* Ws1, const float* Wn1,
                            const float* Ws2, const float* Wn2,
                            const float* Ws3, const float* Wn3,
                            const float* Ws4, const float* Wn4) {
    int i = blockIdx.x * 256 + threadIdx.x;
    if      (i < 8192)  bpack_one(i,         0,     128, 128, Ws1, Wn1);
    else if (i < 12288) bpack_one(i - 8192,  8192,  64,  128, Ws2, Wn2);
    else if (i < 16384) bpack_one(i - 12288, 12288, 64,  128, Ws3, Wn3);
    else if (i < 17408) bpack_one(i - 16384, 16384, 64,  32,  Ws4, Wn4);
}

// ---------------- MMA GEMM v5: tf32 single pass, persistent, B-in-smem -----
// [Ys|Yh] = affine(A) @ [Ws|Wn]. fp32 accum. 296 CTAs (2/SM), grid-stride
// over 128-row tiles; warp tile 32 x 64 (NC=128) / 16 x 32 (NC=32).
template <int K, int NC, bool AFF, bool RELU>
__global__ __launch_bounds__(256, 2) void k_mma(
    const float* __restrict__ A, const uint2* __restrict__ Bf,
    float* __restrict__ Ys, __half* __restrict__ Yh,
    const float* __restrict__ s1, const float* __restrict__ s2,
    const float* __restrict__ gamma, const float* __restrict__ beta,
    int M, int ntiles)
{
    constexpr int KS8   = K / 8;
    constexpr int NTall = NC / 8;
    constexpr int F     = NC / 2;
    constexpr int CGRP  = (NC >= 128) ? 2 : 1;
    constexpr int CPW   = NC / CGRP;
    constexpr int NT    = CPW / 8;
    constexpr int RGRP  = 8 / CGRP;
    constexpr int RPW   = 128 / RGRP;
    constexpr int NROW  = RPW / 16;
    constexpr int SBN   = KS8 * NTall * 32;   // uint2 entries

    extern __shared__ uint2 sB[];
    __shared__ float sAff[128];

    const int tid  = threadIdx.x;
    const int wid  = tid >> 5, lane = tid & 31;
    const int rw   = wid % RGRP, cw = wid / RGRP;
    const int g    = lane >> 2, c = lane & 3;

    for (int i = tid; i < SBN; i += 256) sB[i] = Bf[i];
    if (AFF) {
        if (tid < 64) {
            const float invN = 1.0f / (float)NN;
            float m   = s1[tid] * invN;
            float var = s2[tid] * invN - m * m;
            float r   = rsqrtf(var + 1e-5f);
            float a   = r * gamma[tid];
            sAff[tid]      = a;
            sAff[64 + tid] = fmaf(-m, a, beta[tid]);
        }
    }
    __syncthreads();

    for (int tile = blockIdx.x; tile < ntiles; tile += gridDim.x) {
        const int rowb = tile * 128 + rw * RPW;

        float acc[NROW][NT][4];
        #pragma unroll
        for (int rr = 0; rr < NROW; rr++)
            #pragma unroll
            for (int t = 0; t < NT; t++)
                #pragma unroll
                for (int j = 0; j < 4; j++) acc[rr][t][j] = 0.f;

        #pragma unroll
        for (int s8 = 0; s8 < KS8; s8++) {
            const int k0 = s8 * 8 + c;      // a0/a1 at k0, a2/a3 at k0+4
            uint32_t af[NROW][4];
            #pragma unroll
            for (int rr = 0; rr < NROW; rr++) {
                int r0 = rowb + rr * 16 + g, r1 = r0 + 8;
                float v00 = (r0 < M) ? A[(size_t)r0 * K + k0]     : 0.f;
                float v01 = (r0 < M) ? A[(size_t)r0 * K + k0 + 4] : 0.f;
                float v10 = (r1 < M) ? A[(size_t)r1 * K + k0]     : 0.f;
                float v11 = (r1 < M) ? A[(size_t)r1 * K + k0 + 4] : 0.f;
                if (AFF) {
                    float a0 = sAff[k0],     c0 = sAff[64 + k0];
                    float a1 = sAff[k0 + 4], c1 = sAff[64 + k0 + 4];
                    v00 = fmaf(v00, a0, c0); v10 = fmaf(v10, a0, c0);
                    v01 = fmaf(v01, a1, c1); v11 = fmaf(v11, a1, c1);
                    if (RELU) {
                        v00 = fmaxf(v00, 0.f); v01 = fmaxf(v01, 0.f);
                        v10 = fmaxf(v10, 0.f); v11 = fmaxf(v11, 0.f);
                    }
                }
                af[rr][0] = f2tf32(v00);   // (g,   k0)
                af[rr][1] = f2tf32(v10);   // (g+8, k0)
                af[rr][2] = f2tf32(v01);   // (g,   k0+4)
                af[rr][3] = f2tf32(v11);   // (g+8, k0+4)
            }
            const uint2* bp = sB + (size_t)(s8 * NTall + cw * NT) * 32 + lane;
            #pragma unroll
            for (int t = 0; t < NT; t++) {
                uint2 b = bp[t * 32];
                #pragma unroll
                for (int rr = 0; rr < NROW; rr++)
                    mma_tf32(acc[rr][t], af[rr], b.x, b.y);
            }
        }

        // epilogue: cols [0,F) -> fp32 Ys, [F,NC) -> fp16 Yh
        #pragma unroll
        for (int rr = 0; rr < NROW; rr++) {
            int r0 = rowb + rr * 16 + g, r1 = r0 + 8;
            #pragma unroll
            for (int t = 0; t < NT; t++) {
                int base = cw * CPW + t * 8;
                if (base < F) {
                    int col = base + 2 * c;
                    if (r0 < M)
                        *(float2*)(Ys + (size_t)r0 * F + col) =
                            make_float2(acc[rr][t][0], acc[rr][t][1]);
                    if (r1 < M)
                        *(float2*)(Ys + (size_t)r1 * F + col) =
                            make_float2(acc[rr][t][2], acc[rr][t][3]);
                } else {
                    int col = base - F + 2 * c;
                    if (r0 < M)
                        *(__half2*)(Yh + (size_t)r0 * F + col) =
                            __floats2half2_rn(acc[rr][t][0], acc[rr][t][1]);
                    if (r1 < M)
                        *(__half2*)(Yh + (size_t)r1 * F + col) =
                            __floats2half2_rn(acc[rr][t][2], acc[rr][t][3]);
                }
            }
        }
    }
}

// ---------------- CSR mean-agg + self + bias + BN stats (F=64, fp16 gather) -
__global__ void k_agg64(const float* __restrict__ Ys, const __half2* __restrict__ Yh,
                        const float* __restrict__ bias, float* __restrict__ H,
                        float* __restrict__ s1, float* __restrict__ s2, int M)
{
    __shared__ float ss[128];
    int tid = threadIdx.x;
    if (tid < 128) ss[tid] = 0.f;
    __syncthreads();

    int lane = tid & 31, w = tid >> 5;
    int c0 = lane * 2;
    float bx = bias[c0], by = bias[c0 + 1];
    float p1 = 0.f, p2 = 0.f, q1 = 0.f, q2 = 0.f;

    for (int v = blockIdx.x * 8 + w; v < M; v += gridDim.x * 8) {
        int beg = g_rowptr[v], end = g_rowptr[v + 1];
        float ax0 = 0.f, ay0 = 0.f, ax1 = 0.f, ay1 = 0.f;
        float ax2 = 0.f, ay2 = 0.f, ax3 = 0.f, ay3 = 0.f;
        int e = beg;
        for (; e + 4 <= end; e += 4) {
            int s0 = g_colidx[e],     s1i = g_colidx[e + 1];
            int s2i = g_colidx[e + 2], s3 = g_colidx[e + 3];
            float2 t0 = __half22float2(Yh[(size_t)s0  * 32 + lane]);
            float2 t1 = __half22float2(Yh[(size_t)s1i * 32 + lane]);
            float2 t2 = __half22float2(Yh[(size_t)s2i * 32 + lane]);
            float2 t3 = __half22float2(Yh[(size_t)s3  * 32 + lane]);
            ax0 += t0.x; ay0 += t0.y;
            ax1 += t1.x; ay1 += t1.y;
            ax2 += t2.x; ay2 += t2.y;
            ax3 += t3.x; ay3 += t3.y;
        }
        for (; e < end; e++) {
            int s = g_colidx[e];
            float2 t = __half22float2(Yh[(size_t)s * 32 + lane]);
            ax0 += t.x; ay0 += t.y;
        }
        float ax = (ax0 + ax1) + (ax2 + ax3);
        float ay = (ay0 + ay1) + (ay2 + ay3);
        float di = g_deginv[v];
        float2 ys = *(const float2*)(Ys + (size_t)v * 64 + c0);
        float hx = fmaf(ax, di, ys.x) + bx;
        float hy = fmaf(ay, di, ys.y) + by;
        *(float2*)(H + (size_t)v * 64 + c0) = make_float2(hx, hy);
        p1 += hx; p2 += hx * hx;
        q1 += hy; q2 += hy * hy;
    }
    atomicAdd(&ss[c0], p1);      atomicAdd(&ss[64 + c0], p2);
    atomicAdd(&ss[c0 + 1], q1);  atomicAdd(&ss[64 + c0 + 1], q2);
    __syncthreads();
    if (tid < 64) {
        atomicAdd(&s1[tid], ss[tid]);
        atomicAdd(&s2[tid], ss[64 + tid]);
    }
}

// ---------------- final layer aggregation (F=16, fp16 gather, no BN) -------
__global__ void k_agg16(const float* __restrict__ Ys, const __half* __restrict__ Yh,
                        const float* __restrict__ bias, float* __restrict__ O, int M)
{
    int tid = threadIdx.x, lane = tid & 31, w = tid >> 5;
    bool act = lane < 16;
    float b = act ? bias[lane] : 0.f;
    for (int v = blockIdx.x * 8 + w; v < M; v += gridDim.x * 8) {
        int beg = g_rowptr[v], end = g_rowptr[v + 1];
        float a0 = 0.f, a1 = 0.f, a2 = 0.f, a3 = 0.f;
        int e = beg;
        for (; e + 4 <= end; e += 4) {
            int s0 = g_colidx[e],     s1 = g_colidx[e + 1];
            int s2 = g_colidx[e + 2], s3 = g_colidx[e + 3];
            if (act) {
                float t0 = __half2float(Yh[(size_t)s0 * 16 + lane]);
                float t1 = __half2float(Yh[(size_t)s1 * 16 + lane]);
                float t2 = __half2float(Yh[(size_t)s2 * 16 + lane]);
                float t3 = __half2float(Yh[(size_t)s3 * 16 + lane]);
                a0 += t0; a1 += t1; a2 += t2; a3 += t3;
            }
        }
        for (; e < end; e++) {
            int s = g_colidx[e];
            if (act) a0 += __half2float(Yh[(size_t)s * 16 + lane]);
        }
        if (act) {
            float a = (a0 + a1) + (a2 + a3);
            float ys = Ys[(size_t)v * 16 + lane];
            O[(size_t)v * 16 + lane] = fmaf(a, g_deginv[v], ys) + b;
        }
    }
}

// ---------------- launch ----------------
static constexpr int smem_b(int K, int NC) { return K * NC * 4; }  // tf32 frags

extern "C" void kernel_launch(void* const* d_in, const int* in_sizes, int n_in,
                              void* d_out, int out_size)
{
    const float* x   = (const float*)d_in[0];
    const int*   src = (const int*)d_in[1];
    const int*   dst = (const int*)d_in[2];
    const float* Ws1 = (const float*)d_in[3];
    const float* Wn1 = (const float*)d_in[4];
    const float* b1  = (const float*)d_in[5];
    const float* g1  = (const float*)d_in[6];
    const float* be1 = (const float*)d_in[7];
    const float* Ws2 = (const float*)d_in[8];
    const float* Wn2 = (const float*)d_in[9];
    const float* b2  = (const float*)d_in[10];
    const float* g2  = (const float*)d_in[11];
    const float* be2 = (const float*)d_in[12];
    const float* Ws3 = (const float*)d_in[13];
    const float* Wn3 = (const float*)d_in[14];
    const float* b3  = (const float*)d_in[15];
    const float* g3  = (const float*)d_in[16];
    const float* be3 = (const float*)d_in[17];
    const float* Ws4 = (const float*)d_in[18];
    const float* Wn4 = (const float*)d_in[19];
    const float* b4  = (const float*)d_in[20];
    float* out = (float*)d_out;

    float *Ysp, *Hp, *st1, *st2;
    __half* Yhp;
    uint2* Bfp;
    cudaGetSymbolAddress((void**)&Ysp, g_Ys);
    cudaGetSymbolAddress((void**)&Yhp, g_Yh);
    cudaGetSymbolAddress((void**)&Hp,  g_H);
    cudaGetSymbolAddress((void**)&st1, g_stat1);
    cudaGetSymbolAddress((void**)&st2, g_stat2);
    cudaGetSymbolAddress((void**)&Bfp, g_Bf);

    const int EB = (NE + 255) / 256;
    const int NT128 = (NN + 127) / 128;   // 782 row tiles
    const int GMMA = 296;                 // 2 CTAs/SM, persistent
    const int AGG_GRID = 1184;

    cudaFuncSetAttribute(k_mma<128, 128, false, false>,
        cudaFuncAttributeMaxDynamicSharedMemorySize, smem_b(128, 128));
    cudaFuncSetAttribute(k_mma<64, 128, true, false>,
        cudaFuncAttributeMaxDynamicSharedMemorySize, smem_b(64, 128));
    cudaFuncSetAttribute(k_mma<64, 128, true, true>,
        cudaFuncAttributeMaxDynamicSharedMemorySize, smem_b(64, 128));
    cudaFuncSetAttribute(k_mma<64, 32, true, true>,
        cudaFuncAttributeMaxDynamicSharedMemorySize, smem_b(64, 32));

    // Side stream + fork/join events (created on the two host-executed calls
    // only; replays re-execute captured GPU nodes).
    cudaStream_t s2;
    cudaStreamCreate(&s2);
    cudaEvent_t evFork, evJoin;
    cudaEventCreateWithFlags(&evFork, cudaEventDisableTiming);
    cudaEventCreateWithFlags(&evJoin, cudaEventDisableTiming);

    // main stream: zero counters/stats, then fork
    k_init<<<NBLK, 256>>>();
    cudaEventRecord(evFork, 0);
    cudaStreamWaitEvent(s2, evFork, 0);

    // side stream: CSC (dst-grouped) build — independent of GEMM1/bpack
    k_hist<<<EB, 256, 0, s2>>>(dst);
    k_scan_block<<<NBLK, 256, 0, s2>>>();
    k_scan_tops<<<1, 512, 0, s2>>>(NBLK);
    k_scan_add<<<NBLK, 256, 0, s2>>>();
    k_fill<<<EB, 256, 0, s2>>>(src, dst);
    cudaEventRecord(evJoin, s2);

    // main stream (concurrent with CSC build): weight pack + layer-1 GEMM
    k_bpack_all<<<68, 256>>>(Ws1, Wn1, Ws2, Wn2, Ws3, Wn3, Ws4, Wn4);
    k_mma<128, 128, false, false><<<GMMA, 256, smem_b(128, 128)>>>(
        x, Bfp, Ysp, Yhp, nullptr, nullptr, nullptr, nullptr, NN, NT128);

    // join: aggregation needs both GEMM1 output and the CSC structure
    cudaStreamWaitEvent(0, evJoin, 0);

    k_agg64<<<AGG_GRID, 256>>>(Ysp, (const __half2*)Yhp, b1, Hp, st1, st2, NN);

    k_mma<64, 128, true, false><<<GMMA, 256, smem_b(64, 128)>>>(
        Hp, Bfp + 8192, Ysp, Yhp, st1, st2, g1, be1, NN, NT128);
    k_agg64<<<AGG_GRID, 256>>>(Ysp, (const __half2*)Yhp, b2, Hp, st1 + 64, st2 + 64, NN);

    k_mma<64, 128, true, true><<<GMMA, 256, smem_b(64, 128)>>>(
        Hp, Bfp + 12288, Ysp, Yhp, st1 + 64, st2 + 64, g2, be2, NN, NT128);
    k_agg64<<<AGG_GRID, 256>>>(Ysp, (const __half2*)Yhp, b3, Hp, st1 + 128, st2 + 128, NN);

    k_mma<64, 32, true, true><<<GMMA, 256, smem_b(64, 32)>>>(
        Hp, Bfp + 16384, Ysp, Yhp, st1 + 128, st2 + 128, g3, be3, NN, NT128);
    k_agg16<<<AGG_GRID, 256>>>(Ysp, Yhp, b4, out, NN);
}

// round 17
// speedup vs baseline: 1.5682x; 1.0948x over previous
#include <cuda_runtime.h>
#include <cuda_bf16.h>
#include <cuda_fp16.h>
#include <cstdint>

#define NN 100000
#define NE 1600000
#define NBLK ((NN + 255) / 256)

// ---------------- static device scratch (allocation-free) ----------------
__device__ int    g_cnt[NN];
__device__ int    g_rowptr[NN + 1];
__device__ int    g_cursor[NN];
__device__ int    g_colidx[NE];
__device__ float  g_deginv[NN];
__device__ float  g_Ys[(size_t)NN * 64];   // self-term GEMM output (fp32)
__device__ __half g_Yh[(size_t)NN * 64];   // neighbor-term GEMM output (fp16)
__device__ float  g_H[(size_t)NN * 64];    // hidden activations (pre-BN)
__device__ float  g_stat1[192];            // per-layer BN sums (3 x 64)
__device__ float  g_stat2[192];            // per-layer BN sumsq
__device__ int    g_bsum[512];
__device__ int    g_boff[512];
__device__ uint4  g_Bf[8704];              // packed B frags: L1@0, L2@4096, L3@6144, L4@8192

// ---------------- helpers ----------------
__device__ __forceinline__ void split2(float v0, float v1,
                                       uint32_t& h, uint32_t& l) {
    __nv_bfloat162 hp = __floats2bfloat162_rn(v0, v1);
    float r0 = v0 - __low2float(hp);
    float r1 = v1 - __high2float(hp);
    __nv_bfloat162 lp = __floats2bfloat162_rn(r0, r1);
    h = *(uint32_t*)&hp;
    l = *(uint32_t*)&lp;
}

__device__ __forceinline__ void mma_bf16(float* c, const uint4& a,
                                         uint32_t b0, uint32_t b1) {
    asm volatile(
        "mma.sync.aligned.m16n8k16.row.col.f32.bf16.bf16.f32 "
        "{%0,%1,%2,%3}, {%4,%5,%6,%7}, {%8,%9}, {%0,%1,%2,%3};"
        : "+f"(c[0]), "+f"(c[1]), "+f"(c[2]), "+f"(c[3])
        : "r"(a.x), "r"(a.y), "r"(a.z), "r"(a.w), "r"(b0), "r"(b1));
}

// ---------------- CSR build (R8-proven versions) ----------------
__global__ void k_init() {
    int i = blockIdx.x * 256 + threadIdx.x;
    if (i < NN) g_cnt[i] = 0;
    if (i < 192) { g_stat1[i] = 0.f; g_stat2[i] = 0.f; }
}

__global__ void k_hist(const int* __restrict__ dst) {
    int e = blockIdx.x * 256 + threadIdx.x;
    if (e < NE) atomicAdd(&g_cnt[dst[e]], 1);
}

__global__ void k_scan_block() {
    __shared__ int sh[256];
    int i = blockIdx.x * 256 + threadIdx.x;
    int v = (i < NN) ? g_cnt[i] : 0;
    sh[threadIdx.x] = v;
    __syncthreads();
    #pragma unroll
    for (int off = 1; off < 256; off <<= 1) {
        int t = (threadIdx.x >= off) ? sh[threadIdx.x - off] : 0;
        __syncthreads();
        sh[threadIdx.x] += t;
        __syncthreads();
    }
    if (i < NN) g_rowptr[i] = sh[threadIdx.x] - v;
    if (threadIdx.x == 255) g_bsum[blockIdx.x] = sh[255];
}

__global__ void k_scan_tops(int nb) {
    __shared__ int sh[512];
    int t = threadIdx.x;
    int v = (t < nb) ? g_bsum[t] : 0;
    sh[t] = v;
    __syncthreads();
    #pragma unroll
    for (int off = 1; off < 512; off <<= 1) {
        int tt = (t >= off) ? sh[t - off] : 0;
        __syncthreads();
        sh[t] += tt;
        __syncthreads();
    }
    g_boff[t] = sh[t] - v;
}

__global__ void k_scan_add() {
    int i = blockIdx.x * 256 + threadIdx.x;
    if (i < NN) {
        int rp = g_rowptr[i] + g_boff[blockIdx.x];
        g_rowptr[i] = rp;
        g_cursor[i] = rp;
        int c = g_cnt[i];
        g_deginv[i] = 1.0f / (float)(c > 1 ? c : 1);
    }
    if (blockIdx.x == 0 && threadIdx.x == 0) g_rowptr[NN] = NE;
}

__global__ void k_fill(const int* __restrict__ src, const int* __restrict__ dst) {
    int e = blockIdx.x * 256 + threadIdx.x;
    if (e < NE) {
        int d = dst[e];
        int p = atomicAdd(&g_cursor[d], 1);
        g_colidx[p] = src[e];
    }
}

// ---------------- B fragment pack (bf16 hi/lo, permuted-k layout) ----------
// Logical k for thread c remapped to {4c,4c+1,4c+2,4c+3}: fragment position
// b0 holds logical k 4c,4c+1 and b1 holds 4c+2,4c+3 (A side uses the same
// permutation, so the MMA reduction is exact).
__device__ __forceinline__ void bpack_one(int idx, int base, int K, int NC,
                                          const float* __restrict__ Ws,
                                          const float* __restrict__ Wn) {
    int F = NC / 2, NT = NC / 8;
    int lane = idx & 31, t = (idx >> 5) % NT, s = (idx >> 5) / NT;
    int c = lane & 3, gn = lane >> 2;
    int n = t * 8 + gn;
    int k0 = s * 16 + 4 * c;
    const float* W = (n < F) ? Ws : Wn;
    int nn = (n < F) ? n : n - F;
    float w00 = W[(k0    ) * F + nn];
    float w01 = W[(k0 + 1) * F + nn];
    float w10 = W[(k0 + 2) * F + nn];
    float w11 = W[(k0 + 3) * F + nn];
    uint4 q;
    split2(w00, w01, q.x, q.z);
    split2(w10, w11, q.y, q.w);
    g_Bf[base + idx] = q;
}

__global__ void k_bpack_all(const float* Ws1, const float* Wn1,
                            const float* Ws2, const float* Wn2,
                            const float* Ws3, const float* Wn3,
                            const float* Ws4, const float* Wn4) {
    int i = blockIdx.x * 256 + threadIdx.x;
    if      (i < 4096) bpack_one(i,        0,    128, 128, Ws1, Wn1);
    else if (i < 6144) bpack_one(i - 4096, 4096, 64,  128, Ws2, Wn2);
    else if (i < 8192) bpack_one(i - 6144, 6144, 64,  128, Ws3, Wn3);
    else if (i < 8704) bpack_one(i - 8192, 8192, 64,  32,  Ws4, Wn4);
}

// ---------------- MMA GEMM v6: R12 v2 + float4 A loads (permuted k) --------
// [Ys|Yh] = affine(A) @ [Ws|Wn]. 3-pass bf16 hi/lo split, fp32 accum.
// Persistent 296 CTAs (2/SM), 128-row CTA tile, warp tile 32 x 64 (NC=128).
template <int K, int NC, bool AFF, bool RELU>
__global__ __launch_bounds__(256, 2) void k_mma(
    const float* __restrict__ A, const uint4* __restrict__ Bf,
    float* __restrict__ Ys, __half* __restrict__ Yh,
    const float* __restrict__ s1, const float* __restrict__ s2,
    const float* __restrict__ gamma, const float* __restrict__ beta,
    int M, int ntiles)
{
    constexpr int KS    = K / 16;
    constexpr int NTall = NC / 8;
    constexpr int F     = NC / 2;
    constexpr int CGRP  = (NC >= 128) ? 2 : 1;
    constexpr int CPW   = NC / CGRP;
    constexpr int NT    = CPW / 8;
    constexpr int RGRP  = 8 / CGRP;
    constexpr int RPW   = 128 / RGRP;
    constexpr int NROW  = RPW / 16;
    constexpr int SBN   = KS * NTall * 32;

    extern __shared__ uint4 sB[];
    __shared__ float sAff[128];

    const int tid  = threadIdx.x;
    const int wid  = tid >> 5, lane = tid & 31;
    const int rw   = wid % RGRP, cw = wid / RGRP;
    const int g    = lane >> 2, c = lane & 3;

    for (int i = tid; i < SBN; i += 256) sB[i] = Bf[i];
    if (AFF) {
        if (tid < 64) {
            const float invN = 1.0f / (float)NN;
            float m   = s1[tid] * invN;
            float var = s2[tid] * invN - m * m;
            float r   = rsqrtf(var + 1e-5f);
            float a   = r * gamma[tid];
            sAff[tid]      = a;
            sAff[64 + tid] = fmaf(-m, a, beta[tid]);
        }
    }
    __syncthreads();

    for (int tile = blockIdx.x; tile < ntiles; tile += gridDim.x) {
        const int rowb = tile * 128 + rw * RPW;

        float acc[NROW][NT][4];
        #pragma unroll
        for (int rr = 0; rr < NROW; rr++)
            #pragma unroll
            for (int t = 0; t < NT; t++)
                #pragma unroll
                for (int j = 0; j < 4; j++) acc[rr][t][j] = 0.f;

        #pragma unroll
        for (int s = 0; s < KS; s++) {
            const int k0 = s * 16 + 4 * c;   // this thread's 4 contiguous k
            uint4 ah[NROW], al[NROW];
            #pragma unroll
            for (int rr = 0; rr < NROW; rr++) {
                int r0 = rowb + rr * 16 + g, r1 = r0 + 8;
                float4 v0 = (r0 < M) ? *(const float4*)(A + (size_t)r0 * K + k0)
                                     : make_float4(0.f, 0.f, 0.f, 0.f);
                float4 v1 = (r1 < M) ? *(const float4*)(A + (size_t)r1 * K + k0)
                                     : make_float4(0.f, 0.f, 0.f, 0.f);
                if (AFF) {
                    float a0 = sAff[k0],     c0 = sAff[64 + k0];
                    float a1 = sAff[k0 + 1], c1 = sAff[64 + k0 + 1];
                    float a2 = sAff[k0 + 2], c2 = sAff[64 + k0 + 2];
                    float a3 = sAff[k0 + 3], c3 = sAff[64 + k0 + 3];
                    v0.x = fmaf(v0.x, a0, c0); v0.y = fmaf(v0.y, a1, c1);
                    v0.z = fmaf(v0.z, a2, c2); v0.w = fmaf(v0.w, a3, c3);
                    v1.x = fmaf(v1.x, a0, c0); v1.y = fmaf(v1.y, a1, c1);
                    v1.z = fmaf(v1.z, a2, c2); v1.w = fmaf(v1.w, a3, c3);
                    if (RELU) {
                        v0.x = fmaxf(v0.x, 0.f); v0.y = fmaxf(v0.y, 0.f);
                        v0.z = fmaxf(v0.z, 0.f); v0.w = fmaxf(v0.w, 0.f);
                        v1.x = fmaxf(v1.x, 0.f); v1.y = fmaxf(v1.y, 0.f);
                        v1.z = fmaxf(v1.z, 0.f); v1.w = fmaxf(v1.w, 0.f);
                    }
                }
                // fragment position a0/a1 = logical k 4c,4c+1 (rows g, g+8);
                // a2/a3 = logical k 4c+2,4c+3 — matches bpack permutation
                split2(v0.x, v0.y, ah[rr].x, al[rr].x);
                split2(v1.x, v1.y, ah[rr].y, al[rr].y);
                split2(v0.z, v0.w, ah[rr].z, al[rr].z);
                split2(v1.z, v1.w, ah[rr].w, al[rr].w);
            }
            const uint4* bp = sB + (size_t)(s * NTall + cw * NT) * 32 + lane;
            #pragma unroll
            for (int t = 0; t < NT; t++) {
                uint4 b = bp[t * 32];
                #pragma unroll
                for (int rr = 0; rr < NROW; rr++) {
                    mma_bf16(acc[rr][t], ah[rr], b.x, b.y);   // Ah * Bh
                    mma_bf16(acc[rr][t], ah[rr], b.z, b.w);   // Ah * Bl
                    mma_bf16(acc[rr][t], al[rr], b.x, b.y);   // Al * Bh
                }
            }
        }

        // epilogue: cols [0,F) -> fp32 Ys, [F,NC) -> fp16 Yh
        #pragma unroll
        for (int rr = 0; rr < NROW; rr++) {
            int r0 = rowb + rr * 16 + g, r1 = r0 + 8;
            #pragma unroll
            for (int t = 0; t < NT; t++) {
                int base = cw * CPW + t * 8;
                if (base < F) {
                    int col = base + 2 * c;
                    if (r0 < M)
                        *(float2*)(Ys + (size_t)r0 * F + col) =
                            make_float2(acc[rr][t][0], acc[rr][t][1]);
                    if (r1 < M)
                        *(float2*)(Ys + (size_t)r1 * F + col) =
                            make_float2(acc[rr][t][2], acc[rr][t][3]);
                } else {
                    int col = base - F + 2 * c;
                    if (r0 < M)
                        *(__half2*)(Yh + (size_t)r0 * F + col) =
                            __floats2half2_rn(acc[rr][t][0], acc[rr][t][1]);
                    if (r1 < M)
                        *(__half2*)(Yh + (size_t)r1 * F + col) =
                            __floats2half2_rn(acc[rr][t][2], acc[rr][t][3]);
                }
            }
        }
    }
}

// ---------------- CSR mean-agg + self + bias + BN stats (F=64, fp16 gather) -
__global__ void k_agg64(const float* __restrict__ Ys, const __half2* __restrict__ Yh,
                        const float* __restrict__ bias, float* __restrict__ H,
                        float* __restrict__ s1, float* __restrict__ s2, int M)
{
    __shared__ float ss[128];
    int tid = threadIdx.x;
    if (tid < 128) ss[tid] = 0.f;
    __syncthreads();

    int lane = tid & 31, w = tid >> 5;
    int c0 = lane * 2;
    float bx = bias[c0], by = bias[c0 + 1];
    float p1 = 0.f, p2 = 0.f, q1 = 0.f, q2 = 0.f;

    for (int v = blockIdx.x * 8 + w; v < M; v += gridDim.x * 8) {
        int beg = g_rowptr[v], end = g_rowptr[v + 1];
        float ax0 = 0.f, ay0 = 0.f, ax1 = 0.f, ay1 = 0.f;
        float ax2 = 0.f, ay2 = 0.f, ax3 = 0.f, ay3 = 0.f;
        int e = beg;
        for (; e + 4 <= end; e += 4) {
            int s0 = g_colidx[e],     s1i = g_colidx[e + 1];
            int s2i = g_colidx[e + 2], s3 = g_colidx[e + 3];
            float2 t0 = __half22float2(Yh[(size_t)s0  * 32 + lane]);
            float2 t1 = __half22float2(Yh[(size_t)s1i * 32 + lane]);
            float2 t2 = __half22float2(Yh[(size_t)s2i * 32 + lane]);
            float2 t3 = __half22float2(Yh[(size_t)s3  * 32 + lane]);
            ax0 += t0.x; ay0 += t0.y;
            ax1 += t1.x; ay1 += t1.y;
            ax2 += t2.x; ay2 += t2.y;
            ax3 += t3.x; ay3 += t3.y;
        }
        for (; e < end; e++) {
            int s = g_colidx[e];
            float2 t = __half22float2(Yh[(size_t)s * 32 + lane]);
            ax0 += t.x; ay0 += t.y;
        }
        float ax = (ax0 + ax1) + (ax2 + ax3);
        float ay = (ay0 + ay1) + (ay2 + ay3);
        float di = g_deginv[v];
        float2 ys = *(const float2*)(Ys + (size_t)v * 64 + c0);
        float hx = fmaf(ax, di, ys.x) + bx;
        float hy = fmaf(ay, di, ys.y) + by;
        *(float2*)(H + (size_t)v * 64 + c0) = make_float2(hx, hy);
        p1 += hx; p2 += hx * hx;
        q1 += hy; q2 += hy * hy;
    }
    atomicAdd(&ss[c0], p1);      atomicAdd(&ss[64 + c0], p2);
    atomicAdd(&ss[c0 + 1], q1);  atomicAdd(&ss[64 + c0 + 1], q2);
    __syncthreads();
    if (tid < 64) {
        atomicAdd(&s1[tid], ss[tid]);
        atomicAdd(&s2[tid], ss[64 + tid]);
    }
}

// ---------------- final layer aggregation (F=16, fp16 gather, no BN) -------
__global__ void k_agg16(const float* __restrict__ Ys, const __half* __restrict__ Yh,
                        const float* __restrict__ bias, float* __restrict__ O, int M)
{
    int tid = threadIdx.x, lane = tid & 31, w = tid >> 5;
    bool act = lane < 16;
    float b = act ? bias[lane] : 0.f;
    for (int v = blockIdx.x * 8 + w; v < M; v += gridDim.x * 8) {
        int beg = g_rowptr[v], end = g_rowptr[v + 1];
        float a0 = 0.f, a1 = 0.f, a2 = 0.f, a3 = 0.f;
        int e = beg;
        for (; e + 4 <= end; e += 4) {
            int s0 = g_colidx[e],     s1 = g_colidx[e + 1];
            int s2 = g_colidx[e + 2], s3 = g_colidx[e + 3];
            if (act) {
                float t0 = __half2float(Yh[(size_t)s0 * 16 + lane]);
                float t1 = __half2float(Yh[(size_t)s1 * 16 + lane]);
                float t2 = __half2float(Yh[(size_t)s2 * 16 + lane]);
                float t3 = __half2float(Yh[(size_t)s3 * 16 + lane]);
                a0 += t0; a1 += t1; a2 += t2; a3 += t3;
            }
        }
        for (; e < end; e++) {
            int s = g_colidx[e];
            if (act) a0 += __half2float(Yh[(size_t)s * 16 + lane]);
        }
        if (act) {
            float a = (a0 + a1) + (a2 + a3);
            float ys = Ys[(size_t)v * 16 + lane];
            O[(size_t)v * 16 + lane] = fmaf(a, g_deginv[v], ys) + b;
        }
    }
}

// ---------------- launch ----------------
static constexpr int smem_b(int K, int NC) { return K * NC * 4; }  // hi+lo frags

extern "C" void kernel_launch(void* const* d_in, const int* in_sizes, int n_in,
                              void* d_out, int out_size)
{
    const float* x   = (const float*)d_in[0];
    const int*   src = (const int*)d_in[1];
    const int*   dst = (const int*)d_in[2];
    const float* Ws1 = (const float*)d_in[3];
    const float* Wn1 = (const float*)d_in[4];
    const float* b1  = (const float*)d_in[5];
    const float* g1  = (const float*)d_in[6];
    const float* be1 = (const float*)d_in[7];
    const float* Ws2 = (const float*)d_in[8];
    const float* Wn2 = (const float*)d_in[9];
    const float* b2  = (const float*)d_in[10];
    const float* g2  = (const float*)d_in[11];
    const float* be2 = (const float*)d_in[12];
    const float* Ws3 = (const float*)d_in[13];
    const float* Wn3 = (const float*)d_in[14];
    const float* b3  = (const float*)d_in[15];
    const float* g3  = (const float*)d_in[16];
    const float* be3 = (const float*)d_in[17];
    const float* Ws4 = (const float*)d_in[18];
    const float* Wn4 = (const float*)d_in[19];
    const float* b4  = (const float*)d_in[20];
    float* out = (float*)d_out;

    float *Ysp, *Hp, *st1, *st2;
    __half* Yhp;
    uint4* Bfp;
    cudaGetSymbolAddress((void**)&Ysp, g_Ys);
    cudaGetSymbolAddress((void**)&Yhp, g_Yh);
    cudaGetSymbolAddress((void**)&Hp,  g_H);
    cudaGetSymbolAddress((void**)&st1, g_stat1);
    cudaGetSymbolAddress((void**)&st2, g_stat2);
    cudaGetSymbolAddress((void**)&Bfp, g_Bf);

    const int EB = (NE + 255) / 256;
    const int NT128 = (NN + 127) / 128;   // 782 row tiles
    const int GMMA = 296;                 // 2 CTAs/SM, persistent
    const int AGG_GRID = 1184;

    cudaFuncSetAttribute(k_mma<128, 128, false, false>,
        cudaFuncAttributeMaxDynamicSharedMemorySize, smem_b(128, 128));
    cudaFuncSetAttribute(k_mma<64, 128, true, false>,
        cudaFuncAttributeMaxDynamicSharedMemorySize, smem_b(64, 128));
    cudaFuncSetAttribute(k_mma<64, 128, true, true>,
        cudaFuncAttributeMaxDynamicSharedMemorySize, smem_b(64, 128));
    cudaFuncSetAttribute(k_mma<64, 32, true, true>,
        cudaFuncAttributeMaxDynamicSharedMemorySize, smem_b(64, 32));

    // Side stream + fork/join events (created on the two host-executed calls
    // only; replays re-execute captured GPU nodes).
    cudaStream_t s2;
    cudaStreamCreate(&s2);
    cudaEvent_t evFork, evJoin;
    cudaEventCreateWithFlags(&evFork, cudaEventDisableTiming);
    cudaEventCreateWithFlags(&evJoin, cudaEventDisableTiming);

    // main stream: zero counters/stats, then fork
    k_init<<<NBLK, 256>>>();
    cudaEventRecord(evFork, 0);
    cudaStreamWaitEvent(s2, evFork, 0);

    // side stream: CSC (dst-grouped) build — independent of GEMM1/bpack
    k_hist<<<EB, 256, 0, s2>>>(dst);
    k_scan_block<<<NBLK, 256, 0, s2>>>();
    k_scan_tops<<<1, 512, 0, s2>>>(NBLK);
    k_scan_add<<<NBLK, 256, 0, s2>>>();
    k_fill<<<EB, 256, 0, s2>>>(src, dst);
    cudaEventRecord(evJoin, s2);

    // main stream (concurrent with CSC build): weight pack + layer-1 GEMM
    k_bpack_all<<<34, 256>>>(Ws1, Wn1, Ws2, Wn2, Ws3, Wn3, Ws4, Wn4);
    k_mma<128, 128, false, false><<<GMMA, 256, smem_b(128, 128)>>>(
        x, Bfp, Ysp, Yhp, nullptr, nullptr, nullptr, nullptr, NN, NT128);

    // join: aggregation needs both GEMM1 output and the CSC structure
    cudaStreamWaitEvent(0, evJoin, 0);

    k_agg64<<<AGG_GRID, 256>>>(Ysp, (const __half2*)Yhp, b1, Hp, st1, st2, NN);

    k_mma<64, 128, true, false><<<GMMA, 256, smem_b(64, 128)>>>(
        Hp, Bfp + 4096, Ysp, Yhp, st1, st2, g1, be1, NN, NT128);
    k_agg64<<<AGG_GRID, 256>>>(Ysp, (const __half2*)Yhp, b2, Hp, st1 + 64, st2 + 64, NN);

    k_mma<64, 128, true, true><<<GMMA, 256, smem_b(64, 128)>>>(
        Hp, Bfp + 6144, Ysp, Yhp, st1 + 64, st2 + 64, g2, be2, NN, NT128);
    k_agg64<<<AGG_GRID, 256>>>(Ysp, (const __half2*)Yhp, b3, Hp, st1 + 128, st2 + 128, NN);

    k_mma<64, 32, true, true><<<GMMA, 256, smem_b(64, 32)>>>(
        Hp, Bfp + 8192, Ysp, Yhp, st1 + 128, st2 + 128, g3, be3, NN, NT128);
    k_agg16<<<AGG_GRID, 256>>>(Ysp, Yhp, b4, out, NN);
}